// round 4
// baseline (speedup 1.0000x reference)
#include <cuda_runtime.h>
#include <cuda_bf16.h>

// CenterNet GT heatmap rendering.
// hm:      [N, C, H, W] f32 (shape-only)      -> d_in[0]
// bboxes:  [N, NOBJ, 5] f32 (x1,y1,x2,y2,val) -> d_in[1]
// out:     [N, C, H, W] f32, C == 1
//
// Strategy: scatter. One block per (batch, object); render only the
// (2r+1)x(2r+1) gaussian patch and atomicMax (float-as-int, valid since
// all values are >= 0) into the per-batch plane. Output is zero-initialized
// by a separate vectorized kernel (harness poisons d_out to 0xAA).

#define HN 16
#define HC 1
#define HH 128
#define HW 128
#define NOBJ 128
#define MIN_OVERLAP 0.7f

__global__ void cn_init_kernel(float4* __restrict__ out) {
    int i = blockIdx.x * blockDim.x + threadIdx.x;
    out[i] = make_float4(0.f, 0.f, 0.f, 0.f);
}

__device__ __forceinline__ float gaussian_radius_f(float w, float h) {
    // mirrors the reference fp32 math op-for-op
    const float mo = MIN_OVERLAP;
    float b1 = h + w;
    float c1 = w * h * (1.0f - mo) / (1.0f + mo);
    float sq1 = sqrtf(b1 * b1 - 4.0f * 1.0f * c1);
    float r1 = (b1 + sq1) * 0.5f;

    float b2 = 2.0f * (h + w);
    float c2 = (1.0f - mo) * w * h;
    float sq2 = sqrtf(b2 * b2 - 4.0f * 4.0f * c2);
    float r2 = (b2 + sq2) * 0.5f;

    float a3 = 4.0f * mo;
    float b3 = -2.0f * mo * (h + w);
    float c3 = (mo - 1.0f) * w * h;
    float sq3 = sqrtf(b3 * b3 - 4.0f * a3 * c3);
    float r3 = (b3 + sq3) * 0.5f;

    return fminf(fminf(r1, r2), r3);
}

__global__ void cn_scatter_kernel(const float* __restrict__ bboxes,
                                  float* __restrict__ out) {
    const int obj   = blockIdx.x;   // 0..NOBJ-1
    const int batch = blockIdx.y;   // 0..HN-1

    // All threads redundantly compute the per-object params (cheap; avoids
    // smem + sync). Loads hit L1/L2 broadcast.
    const float* p = bboxes + (batch * NOBJ + obj) * 5;
    float x1 = p[0] * (float)HW;
    float y1 = p[1] * (float)HH;
    float x2 = p[2] * (float)HW;
    float y2 = p[3] * (float)HH;
    float valf = p[4];
    float bw = x2 - x1;
    float bh = y2 - y1;

    if (!(valf == 1.0f && bw > 0.0f && bh > 0.0f)) return;

    float r = gaussian_radius_f(bw, bh);
    if (!(r == r)) r = 0.0f;       // jnp.nan_to_num
    r = fmaxf(r, 0.0f);

    int ri  = (int)r;                          // trunc toward zero, r >= 0
    int cxi = (int)((x1 + x2) * 0.5f);
    int cyi = (int)((y1 + y2) * 0.5f);

    float sigma = (float)(2 * ri + 1) / 6.0f;
    float two_sig2 = 2.0f * sigma * sigma;

    // clipped patch bounds (inside <=> |dx|<=ri && |dy|<=ri)
    int px0 = max(cxi - ri, 0);
    int px1 = min(cxi + ri, HW - 1);
    int py0 = max(cyi - ri, 0);
    int py1 = min(cyi + ri, HH - 1);
    if (px1 < px0 || py1 < py0) return;

    int pw  = px1 - px0 + 1;
    int tot = pw * (py1 - py0 + 1);

    float* dst = out + batch * (HH * HW);   // C == 1

    for (int i = threadIdx.x; i < tot; i += blockDim.x) {
        int yy = py0 + i / pw;
        int xx = px0 + i % pw;
        int dx = xx - cxi;
        int dy = yy - cyi;
        float d2 = (float)(dx * dx + dy * dy);
        float g = expf(-d2 / two_sig2);
        // float atomicMax via int compare: valid for non-negative floats
        atomicMax((int*)(dst + yy * HW + xx), __float_as_int(g));
    }
}

extern "C" void kernel_launch(void* const* d_in, const int* in_sizes, int n_in,
                              void* d_out, int out_size) {
    const float* bboxes = (const float*)d_in[1];
    float* out = (float*)d_out;

    // out_size = 16*1*128*128 = 262144 floats = 65536 float4
    const int total4 = (HN * HC * HH * HW) / 4;
    cn_init_kernel<<<total4 / 256, 256>>>((float4*)out);

    dim3 grid(NOBJ, HN);
    cn_scatter_kernel<<<grid, 128>>>(bboxes, out);
}

// round 5
// speedup vs baseline: 1.0685x; 1.0685x over previous
#include <cuda_runtime.h>
#include <cuda_bf16.h>

// CenterNet GT heatmap rendering.
// hm:      [N, C, H, W] f32 (shape-only)      -> d_in[0]
// bboxes:  [N, NOBJ, 5] f32 (x1,y1,x2,y2,val) -> d_in[1]
// out:     [N, C, H, W] f32, C == 1
//
// Strategy: scatter. One block per (batch, object); render only the
// (2r+1)x(2r+1) gaussian patch and atomicMax (float-as-int, valid since
// all values are >= 0) into the per-batch plane. Output is zero-initialized
// by a separate vectorized kernel (harness poisons d_out to 0xAA).

#define HN 16
#define HC 1
#define HH 128
#define HW 128
#define NOBJ 128
#define MIN_OVERLAP 0.7f

__global__ void cn_init_kernel(float4* __restrict__ out) {
    int i = blockIdx.x * blockDim.x + threadIdx.x;
    out[i] = make_float4(0.f, 0.f, 0.f, 0.f);
}

__device__ __forceinline__ float gaussian_radius_f(float w, float h) {
    // mirrors the reference fp32 math op-for-op
    const float mo = MIN_OVERLAP;
    float b1 = h + w;
    float c1 = w * h * (1.0f - mo) / (1.0f + mo);
    float sq1 = sqrtf(b1 * b1 - 4.0f * 1.0f * c1);
    float r1 = (b1 + sq1) * 0.5f;

    float b2 = 2.0f * (h + w);
    float c2 = (1.0f - mo) * w * h;
    float sq2 = sqrtf(b2 * b2 - 4.0f * 4.0f * c2);
    float r2 = (b2 + sq2) * 0.5f;

    float a3 = 4.0f * mo;
    float b3 = -2.0f * mo * (h + w);
    float c3 = (mo - 1.0f) * w * h;
    float sq3 = sqrtf(b3 * b3 - 4.0f * a3 * c3);
    float r3 = (b3 + sq3) * 0.5f;

    return fminf(fminf(r1, r2), r3);
}

__global__ void cn_scatter_kernel(const float* __restrict__ bboxes,
                                  float* __restrict__ out) {
    const int obj   = blockIdx.x;   // 0..NOBJ-1
    const int batch = blockIdx.y;   // 0..HN-1

    // All threads redundantly compute the per-object params (cheap; avoids
    // smem + sync). Loads hit L1/L2 broadcast.
    const float* p = bboxes + (batch * NOBJ + obj) * 5;
    float x1 = p[0] * (float)HW;
    float y1 = p[1] * (float)HH;
    float x2 = p[2] * (float)HW;
    float y2 = p[3] * (float)HH;
    float valf = p[4];
    float bw = x2 - x1;
    float bh = y2 - y1;

    if (!(valf == 1.0f && bw > 0.0f && bh > 0.0f)) return;

    float r = gaussian_radius_f(bw, bh);
    if (!(r == r)) r = 0.0f;       // jnp.nan_to_num
    r = fmaxf(r, 0.0f);

    int ri  = (int)r;                          // trunc toward zero, r >= 0
    int cxi = (int)((x1 + x2) * 0.5f);
    int cyi = (int)((y1 + y2) * 0.5f);

    float sigma = (float)(2 * ri + 1) / 6.0f;
    float two_sig2 = 2.0f * sigma * sigma;

    // clipped patch bounds (inside <=> |dx|<=ri && |dy|<=ri)
    int px0 = max(cxi - ri, 0);
    int px1 = min(cxi + ri, HW - 1);
    int py0 = max(cyi - ri, 0);
    int py1 = min(cyi + ri, HH - 1);
    if (px1 < px0 || py1 < py0) return;

    int pw  = px1 - px0 + 1;
    int tot = pw * (py1 - py0 + 1);

    float* dst = out + batch * (HH * HW);   // C == 1

    for (int i = threadIdx.x; i < tot; i += blockDim.x) {
        int yy = py0 + i / pw;
        int xx = px0 + i % pw;
        int dx = xx - cxi;
        int dy = yy - cyi;
        float d2 = (float)(dx * dx + dy * dy);
        float g = expf(-d2 / two_sig2);
        // float atomicMax via int compare: valid for non-negative floats
        atomicMax((int*)(dst + yy * HW + xx), __float_as_int(g));
    }
}

extern "C" void kernel_launch(void* const* d_in, const int* in_sizes, int n_in,
                              void* d_out, int out_size) {
    const float* bboxes = (const float*)d_in[1];
    float* out = (float*)d_out;

    // out_size = 16*1*128*128 = 262144 floats = 65536 float4
    const int total4 = (HN * HC * HH * HW) / 4;
    cn_init_kernel<<<total4 / 256, 256>>>((float4*)out);

    dim3 grid(NOBJ, HN);
    cn_scatter_kernel<<<grid, 128>>>(bboxes, out);
}

// round 6
// speedup vs baseline: 1.2657x; 1.1845x over previous
#include <cuda_runtime.h>
#include <cuda_bf16.h>

// CenterNet GT heatmap rendering.
// hm:      [N, C, H, W] f32 (shape-only)      -> d_in[0]
// bboxes:  [N, NOBJ, 5] f32 (x1,y1,x2,y2,val) -> d_in[1]
// out:     [N, C, H, W] f32, C == 1
//
// Strategy: scatter, warp-per-object. 8 objects per 256-thread block so the
// bbox-load latency and block setup are amortized across 8 warps on one SM.
// Gaussian values are >= 0, so float max == signed-int max on the bit
// patterns; atomicMax(int) with discarded return compiles to RED.MAX (REDG).

#define HN 16
#define HC 1
#define HH 128
#define HW 128
#define NOBJ 128
#define OBJ_PER_BLK 8
#define MIN_OVERLAP 0.7f

__global__ void cn_init_kernel(float4* __restrict__ out) {
    int i = blockIdx.x * blockDim.x + threadIdx.x;
    out[i] = make_float4(0.f, 0.f, 0.f, 0.f);
}

__device__ __forceinline__ float gaussian_radius_f(float w, float h) {
    // mirrors the reference fp32 math op-for-op
    const float mo = MIN_OVERLAP;
    float b1 = h + w;
    float c1 = w * h * (1.0f - mo) / (1.0f + mo);
    float sq1 = sqrtf(b1 * b1 - 4.0f * 1.0f * c1);
    float r1 = (b1 + sq1) * 0.5f;

    float b2 = 2.0f * (h + w);
    float c2 = (1.0f - mo) * w * h;
    float sq2 = sqrtf(b2 * b2 - 4.0f * 4.0f * c2);
    float r2 = (b2 + sq2) * 0.5f;

    float a3 = 4.0f * mo;
    float b3 = -2.0f * mo * (h + w);
    float c3 = (mo - 1.0f) * w * h;
    float sq3 = sqrtf(b3 * b3 - 4.0f * a3 * c3);
    float r3 = (b3 + sq3) * 0.5f;

    return fminf(fminf(r1, r2), r3);
}

__global__ void __launch_bounds__(OBJ_PER_BLK * 32)
cn_scatter_kernel(const float* __restrict__ bboxes,
                  float* __restrict__ out) {
    const int wid   = threadIdx.x >> 5;                 // warp in block
    const int lane  = threadIdx.x & 31;
    const int obj   = blockIdx.x * OBJ_PER_BLK + wid;   // 0..NOBJ-1
    const int batch = blockIdx.y;                       // 0..HN-1

    // All lanes redundantly load the 5 params (L1 broadcast) and compute the
    // per-object constants — redundant ALU/MUFU across lanes is free here.
    const float* p = bboxes + (batch * NOBJ + obj) * 5;
    float x1 = p[0] * (float)HW;
    float y1 = p[1] * (float)HH;
    float x2 = p[2] * (float)HW;
    float y2 = p[3] * (float)HH;
    float valf = p[4];
    float bw = x2 - x1;
    float bh = y2 - y1;

    if (!(valf == 1.0f && bw > 0.0f && bh > 0.0f)) return;  // warp-uniform

    float r = gaussian_radius_f(bw, bh);
    if (!(r == r)) r = 0.0f;       // jnp.nan_to_num
    r = fmaxf(r, 0.0f);

    int ri  = (int)r;                          // trunc toward zero, r >= 0
    int cxi = (int)((x1 + x2) * 0.5f);
    int cyi = (int)((y1 + y2) * 0.5f);

    float sigma = (float)(2 * ri + 1) / 6.0f;
    float neg_inv_2s2 = -1.0f / (2.0f * sigma * sigma);

    // clipped patch bounds (inside <=> |dx|<=ri && |dy|<=ri)
    int px0 = max(cxi - ri, 0);
    int px1 = min(cxi + ri, HW - 1);
    int py0 = max(cyi - ri, 0);
    int py1 = min(cyi + ri, HH - 1);
    if (px1 < px0 || py1 < py0) return;

    int pw  = px1 - px0 + 1;
    int tot = pw * (py1 - py0 + 1);

    float* dst = out + batch * (HH * HW);   // C == 1

    for (int i = lane; i < tot; i += 32) {
        int yy = py0 + i / pw;
        int xx = px0 + i % pw;
        int dx = xx - cxi;
        int dy = yy - cyi;
        float d2 = (float)(dx * dx + dy * dy);
        float g = __expf(d2 * neg_inv_2s2);
        // float atomicMax via signed-int compare: valid for non-negative
        // floats; discarded return -> RED.MAX.
        atomicMax((int*)(dst + yy * HW + xx), __float_as_int(g));
    }
}

extern "C" void kernel_launch(void* const* d_in, const int* in_sizes, int n_in,
                              void* d_out, int out_size) {
    const float* bboxes = (const float*)d_in[1];
    float* out = (float*)d_out;

    // out_size = 16*1*128*128 = 262144 floats = 65536 float4
    cn_init_kernel<<<256, 256>>>((float4*)out);

    dim3 grid(NOBJ / OBJ_PER_BLK, HN);   // (16, 16)
    cn_scatter_kernel<<<grid, OBJ_PER_BLK * 32>>>(bboxes, out);
}